// round 15
// baseline (speedup 1.0000x reference)
#include <cuda_runtime.h>
#include <cuda_bf16.h>
#include <math.h>

#define Bq 2
#define Nq 2048
#define Fq 128
#define Mq 8
#define Uq 64
#define NM (Nq * Mq)            // 16384 rows of A'
#define OUTSZ (Bq * Nq * Mq * Uq)

#define JC 64                   // j per stage (main)
#define NSTAGE (Nq / JC)        // 32

// ---- main kernel smem: 2-buffer ring, 64-row CTA tile.
// A: j-major [64 j][64 rows bf16 = 128B, XOR-swizzled 16B chunks] hi+lo.
// B: [64 u][64 j bf16 = 128B data, stride 144] hi+lo (filled via cp.async).
#define SAJ 128
#define SBJ 144
#define AH_OFF 0
#define AL_OFF (AH_OFF + 64 * SAJ)      //  8192
#define BH_OFF (AL_OFF + 64 * SAJ)      // 16384
#define BL_OFF (BH_OFF + 64 * SBJ)      // 25600
#define BUF_SZ (BL_OFF + 64 * SBJ)      // 34816
#define SMEM_MAIN (2 * BUF_SZ)          // 69632  (x3 CTA = 208.9KB)

// ---- precompute-mma smem (unchanged)
#define SA2 272
#define P_AH 0
#define P_AL (P_AH + 128 * SA2)
#define P_WH (P_AL + 128 * SA2)
#define P_WL (P_WH + 64 * SA2)
#define SMEM_PRE (P_WL + 64 * SA2)      // 104448
#define CS 66
#define WS 69

// device scratch (allocation-free rule)
__device__ float g_alpha[OUTSZ];
__device__ unsigned short g_bTh[Bq * Uq * Nq];   // betaT hi bf16 [b][u][n]
__device__ unsigned short g_bTl[Bq * Uq * Nq];   // betaT lo bf16

__device__ __forceinline__ unsigned smem_u32(const void* p) {
    unsigned r;
    asm("{ .reg .u64 t; cvta.to.shared.u64 t, %1; cvt.u32.u64 %0, t; }"
        : "=r"(r) : "l"(p));
    return r;
}
__device__ __forceinline__ unsigned cvt_bf16x2(float lo_elem, float hi_elem) {
    unsigned r;   // low 16 bits <- lo_elem, high <- hi_elem
    asm("cvt.rn.bf16x2.f32 %0, %1, %2;" : "=r"(r) : "f"(hi_elem), "f"(lo_elem));
    return r;
}
__device__ __forceinline__ float bf_lo_f(unsigned h) { return __uint_as_float(h << 16); }
__device__ __forceinline__ float bf_hi_f(unsigned h) { return __uint_as_float(h & 0xffff0000u); }

#define LDSM4(r0, r1, r2, r3, addr) \
    asm volatile("ldmatrix.sync.aligned.m8n8.x4.shared.b16 {%0,%1,%2,%3}, [%4];" \
                 : "=r"(r0), "=r"(r1), "=r"(r2), "=r"(r3) : "r"(addr))

#define LDSM4T(r0, r1, r2, r3, addr) \
    asm volatile("ldmatrix.sync.aligned.m8n8.x4.trans.shared.b16 {%0,%1,%2,%3}, [%4];" \
                 : "=r"(r0), "=r"(r1), "=r"(r2), "=r"(r3) : "r"(addr))

#define CP_ASYNC16(dst, src) \
    asm volatile("cp.async.cg.shared.global [%0], [%1], 16;" :: "r"(dst), "l"(src))
#define CP_COMMIT() asm volatile("cp.async.commit_group;" ::: "memory")
#define CP_WAIT0()  asm volatile("cp.async.wait_group 0;" ::: "memory")

__device__ __forceinline__ void mma_bf16(float* c, const unsigned* a, const unsigned* b) {
    asm volatile(
        "mma.sync.aligned.m16n8k16.row.col.f32.bf16.bf16.f32 "
        "{%0,%1,%2,%3}, {%4,%5,%6,%7}, {%8,%9}, {%0,%1,%2,%3};"
        : "+f"(c[0]), "+f"(c[1]), "+f"(c[2]), "+f"(c[3])
        : "r"(a[0]), "r"(a[1]), "r"(a[2]), "r"(a[3]), "r"(b[0]), "r"(b[1]));
}

// ---------------------------------------------------------------------------
// Kernel P: beta|alpha = seq @ [e_w | v_w]  (UNCHANGED)
// ---------------------------------------------------------------------------
__global__ void __launch_bounds__(256, 2) precompute_mma_kernel(
        const float* __restrict__ seq,
        const float* __restrict__ e_w,
        const float* __restrict__ v_w) {
    extern __shared__ __align__(16) char ps[];
    const unsigned sb = smem_u32(ps);

    const int tid = threadIdx.x;
    const int l = tid & 31;
    const int w = tid >> 5;
    const int wr = w >> 1;
    const int wc = w & 1;

    const int bx = blockIdx.x;
    const int by = blockIdx.y;
    const int n0 = by * 128;

    {
        const float* wsrc;
        int wstride, c0;
        if (bx == 0) { wsrc = e_w; wstride = Uq;      c0 = 0; }
        else         { wsrc = v_w; wstride = Mq * Uq; c0 = (bx - 1) * 64; }
        float* wb = (float*)ps;
#pragma unroll
        for (int it = 0; it < 8; it++) {
            int v = tid + it * 256;
            int f = v >> 4, cq = (v & 15) * 4;
            float4 t = *(const float4*)&wsrc[f * wstride + c0 + cq];
            wb[f * WS + cq + 0] = t.x; wb[f * WS + cq + 1] = t.y;
            wb[f * WS + cq + 2] = t.z; wb[f * WS + cq + 3] = t.w;
        }
    }
    __syncthreads();

    {
        const float* wb = (const float*)ps;
        const int c = tid >> 2;
        const int fq8 = tid & 3;
#pragma unroll
        for (int it = 0; it < 4; it++) {
            int f0 = (fq8 + it * 4) * 8;
            unsigned h[4], lo[4];
#pragma unroll
            for (int k = 0; k < 4; k++) {
                float a0 = wb[(f0 + 2 * k) * WS + c];
                float a1 = wb[(f0 + 2 * k + 1) * WS + c];
                h[k] = cvt_bf16x2(a0, a1);
                float r0 = a0 - bf_lo_f(h[k]);
                float r1 = a1 - bf_hi_f(h[k]);
                lo[k] = cvt_bf16x2(r0, r1);
            }
            unsigned off = (unsigned)c * SA2 + f0 * 2;
            *(uint4*)(ps + P_WH + off) = make_uint4(h[0], h[1], h[2], h[3]);
            *(uint4*)(ps + P_WL + off) = make_uint4(lo[0], lo[1], lo[2], lo[3]);
        }
    }
    __syncthreads();

#pragma unroll
    for (int it = 0; it < 16; it++) {
        int v = tid + it * 256;
        int r = v >> 5, fq = v & 31;
        float4 t = *(const float4*)&seq[(size_t)(n0 + r) * Fq + fq * 4];
        unsigned h0 = cvt_bf16x2(t.x, t.y), h1 = cvt_bf16x2(t.z, t.w);
        unsigned l0 = cvt_bf16x2(t.x - bf_lo_f(h0), t.y - bf_hi_f(h0));
        unsigned l1 = cvt_bf16x2(t.z - bf_lo_f(h1), t.w - bf_hi_f(h1));
        unsigned off = (unsigned)r * SA2 + fq * 8;
        *(uint2*)(ps + P_AH + off) = make_uint2(h0, h1);
        *(uint2*)(ps + P_AL + off) = make_uint2(l0, l1);
    }
    __syncthreads();

    float acc[2][4][4];
#pragma unroll
    for (int rt = 0; rt < 2; rt++)
#pragma unroll
        for (int nt = 0; nt < 4; nt++)
#pragma unroll
            for (int k = 0; k < 4; k++) acc[rt][nt][k] = 0.f;

    const unsigned aRow = (unsigned)(wr * 32 + (l & 15)) * SA2 + ((l >> 4) * 16);
    const unsigned bRow = (unsigned)(wc * 32 + (l & 7) + ((l >> 4) & 1) * 8) * SA2
                        + (((l >> 3) & 1) * 16);

#pragma unroll
    for (int ks = 0; ks < 8; ks++) {
        unsigned ah[2][4], al[2][4], bh[8], bl[8];
#pragma unroll
        for (int rt = 0; rt < 2; rt++) {
            unsigned aoff = aRow + (unsigned)rt * 16 * SA2 + ks * 32;
            LDSM4(ah[rt][0], ah[rt][1], ah[rt][2], ah[rt][3], sb + P_AH + aoff);
            LDSM4(al[rt][0], al[rt][1], al[rt][2], al[rt][3], sb + P_AL + aoff);
        }
#pragma unroll
        for (int g = 0; g < 2; g++) {
            unsigned boff = bRow + (unsigned)g * 16 * SA2 + ks * 32;
            LDSM4(bh[g*4+0], bh[g*4+1], bh[g*4+2], bh[g*4+3], sb + P_WH + boff);
            LDSM4(bl[g*4+0], bl[g*4+1], bl[g*4+2], bl[g*4+3], sb + P_WL + boff);
        }
#pragma unroll
        for (int rt = 0; rt < 2; rt++)
#pragma unroll
            for (int nt = 0; nt < 4; nt++) {
                mma_bf16(acc[rt][nt], ah[rt], &bh[nt * 2]);
                mma_bf16(acc[rt][nt], al[rt], &bh[nt * 2]);
                mma_bf16(acc[rt][nt], ah[rt], &bl[nt * 2]);
            }
    }

    if (bx > 0) {
        const int c0 = (bx - 1) * 64;
#pragma unroll
        for (int rt = 0; rt < 2; rt++) {
            const int r0 = n0 + wr * 32 + rt * 16 + (l >> 2);
#pragma unroll
            for (int nt = 0; nt < 4; nt++) {
                const int cu = c0 + wc * 32 + nt * 8 + (l & 3) * 2;
                const size_t idx0 = (size_t)r0 * (Mq * Uq) + cu;
                const size_t idx8 = idx0 + 8 * (Mq * Uq);
                *(float2*)&g_alpha[idx0] = make_float2(acc[rt][nt][0], acc[rt][nt][1]);
                *(float2*)&g_alpha[idx8] = make_float2(acc[rt][nt][2], acc[rt][nt][3]);
            }
        }
    } else {
        __syncthreads();
        float* cs = (float*)ps;
#pragma unroll
        for (int rt = 0; rt < 2; rt++) {
            const int r0 = wr * 32 + rt * 16 + (l >> 2);
#pragma unroll
            for (int nt = 0; nt < 4; nt++) {
                const int u = wc * 32 + nt * 8 + (l & 3) * 2;
                *(float2*)&cs[r0 * CS + u] = make_float2(acc[rt][nt][0], acc[rt][nt][1]);
                *(float2*)&cs[(r0 + 8) * CS + u] = make_float2(acc[rt][nt][2], acc[rt][nt][3]);
            }
        }
        __syncthreads();
        const int b   = n0 >> 11;
        const int nin = n0 & 2047;
        const int u  = tid >> 2;
        const int nq = tid & 3;
#pragma unroll
        for (int it = 0; it < 8; it++) {
            int n = nq * 4 + it * 16;
            float v0 = cs[(n + 0) * CS + u], v1 = cs[(n + 1) * CS + u];
            float v2 = cs[(n + 2) * CS + u], v3 = cs[(n + 3) * CS + u];
            unsigned h01 = cvt_bf16x2(v0, v1), h23 = cvt_bf16x2(v2, v3);
            unsigned l01 = cvt_bf16x2(v0 - bf_lo_f(h01), v1 - bf_hi_f(h01));
            unsigned l23 = cvt_bf16x2(v2 - bf_lo_f(h23), v3 - bf_hi_f(h23));
            size_t idx = (size_t)(b * Uq + u) * Nq + nin + n;
            *(uint2*)&g_bTh[idx] = make_uint2(h01, h23);
            *(uint2*)&g_bTl[idx] = make_uint2(l01, l23);
        }
    }
}

// ---------------------------------------------------------------------------
// Kernel B (main): 64-row x 128-thread CTAs, 3 CTAs/SM (512-CTA grid),
// exact R13 stage schedule (2-ks LDG->STS cover), JC=64, 2-buffer ring.
// Independent CTAs de-sync barrier drains; finer grid kills wave imbalance.
// ---------------------------------------------------------------------------
__global__ void __launch_bounds__(128, 3) multigraph_mma_kernel(
        const float* __restrict__ graph,
        float* __restrict__ out) {
    extern __shared__ __align__(16) char smem[];
    const unsigned sb = smem_u32(smem);

    const int tid = threadIdx.x;
    const int l = tid & 31;
    const int w = tid >> 5;                  // 0..3
    const int wr = w >> 1;                   // 0..1 (32 rows)
    const int wc = w & 1;                    // 0..1 (32 u)

    const int rt0 = blockIdx.x * 64;         // global A' row base
    const int b   = blockIdx.y;
    const int i0  = rt0 >> 3;                // 8 i per CTA tile

    // A staging: lane pair covers (jp, mq); thread covers 8 il in 2 halves
    const int mq  = tid & 1;
    const int jp  = tid >> 1;                // 0..63
    const int jp7 = jp & 7;
    // B cp.async mapping: u = tid>>1, half = tid&1 (4 chunks each)
    const int bu  = tid >> 1;                // 0..63
    const int bh4 = (tid & 1) * 4;

    float acc[2][4][4];
#pragma unroll
    for (int rt = 0; rt < 2; rt++)
#pragma unroll
        for (int nt = 0; nt < 4; nt++)
#pragma unroll
            for (int k = 0; k < 4; k++) acc[rt][nt][k] = 0.f;

    // ldmatrix lane constants
    const int jl15 = (l & 7) + ((l >> 4) & 1) * 8;   // j within 16-group
    const int cpart = (l >> 3) & 1;                   // 8-row subgroup
    const unsigned bRow = (unsigned)(wc * 32 + (l & 7) + ((l >> 4) & 1) * 8) * SBJ
                        + (unsigned)(cpart * 16);

    const size_t gbase = ((size_t)b * Nq + i0) * Nq * Mq;
    const size_t bTb = (size_t)b * Uq * Nq;

    float4 av[4];

    auto ldgA = [&](int s, int h) {
        const int j0 = s * JC;
#pragma unroll
        for (int c = 0; c < 4; c++) {
            int il = h * 4 + c;              // 0..7
            av[c] = *(const float4*)(graph + gbase
                        + ((size_t)il * Nq + j0 + jp) * Mq + mq * 4);
        }
    };
    auto stsA = [&](int p, int h) {
        char* buf = smem + p * BUF_SZ;
#pragma unroll
        for (int c = 0; c < 4; c++) {
            int il = h * 4 + c;              // chunk index 0..7
            const float* v = (const float*)&av[c];
            unsigned h0 = cvt_bf16x2(v[0], v[1]);
            unsigned h1 = cvt_bf16x2(v[2], v[3]);
            unsigned l0 = cvt_bf16x2(v[0] - bf_lo_f(h0), v[1] - bf_hi_f(h0));
            unsigned l1 = cvt_bf16x2(v[2] - bf_lo_f(h1), v[3] - bf_hi_f(h1));
            unsigned off = (unsigned)jp * SAJ + (unsigned)((il ^ jp7) << 4)
                         + (unsigned)(mq * 8);
            *(uint2*)(buf + AH_OFF + off) = make_uint2(h0, h1);
            *(uint2*)(buf + AL_OFF + off) = make_uint2(l0, l1);
        }
    };
    auto cpaB = [&](int s, int p) {
        const int j0 = s * JC;
        const unsigned dbase = sb + (unsigned)p * BUF_SZ;
#pragma unroll
        for (int k = 0; k < 4; k++) {
            int jq = bh4 + k;                // 0..7
            size_t src = bTb + (size_t)bu * Nq + j0 + jq * 8;
            unsigned doff = (unsigned)bu * SBJ + jq * 16;
            CP_ASYNC16(dbase + BH_OFF + doff, (const char*)&g_bTh[src]);
            CP_ASYNC16(dbase + BL_OFF + doff, (const char*)&g_bTl[src]);
        }
    };
    auto mmaKs = [&](int p, int ks) {
        const unsigned base = sb + (unsigned)p * BUF_SZ;
        const int jrow = jl15 + ks * 16;
        unsigned ah[2][4], al[2][4], bh[8], bl[8];
#pragma unroll
        for (int rt = 0; rt < 2; rt++) {
            int chunk = wr * 4 + rt * 2 + cpart;     // 0..7
            unsigned aoff = (unsigned)jrow * SAJ
                          + (unsigned)((chunk ^ (jrow & 7)) << 4);
            LDSM4T(ah[rt][0], ah[rt][1], ah[rt][2], ah[rt][3], base + AH_OFF + aoff);
            LDSM4T(al[rt][0], al[rt][1], al[rt][2], al[rt][3], base + AL_OFF + aoff);
        }
#pragma unroll
        for (int g = 0; g < 2; g++) {
            unsigned boff = bRow + (unsigned)g * 16 * SBJ + ks * 32;
            LDSM4(bh[g*4+0], bh[g*4+1], bh[g*4+2], bh[g*4+3], base + BH_OFF + boff);
            LDSM4(bl[g*4+0], bl[g*4+1], bl[g*4+2], bl[g*4+3], base + BL_OFF + boff);
        }
#pragma unroll
        for (int rt = 0; rt < 2; rt++)
#pragma unroll
            for (int nt = 0; nt < 4; nt++) {
                mma_bf16(acc[rt][nt], ah[rt], &bh[nt * 2]);
                mma_bf16(acc[rt][nt], al[rt], &bh[nt * 2]);
                mma_bf16(acc[rt][nt], ah[rt], &bl[nt * 2]);
            }
    };

    // prologue: stage 0 fully staged into buffer 0
    ldgA(0, 0); stsA(0, 0);
    ldgA(0, 1); stsA(0, 1);
    cpaB(0, 0); CP_COMMIT();
    CP_WAIT0();

    int pm = 0;
#pragma unroll 1
    for (int s = 0; s < NSTAGE; s++) {
        __syncthreads();                     // buf pm ready; buf pn free
        const int pn = pm ^ 1;
        const bool s1 = (s + 1 < NSTAGE);
        if (s1) ldgA(s + 1, 0);
        mmaKs(pm, 0);
        mmaKs(pm, 1);
        if (s1) {
            stsA(pn, 0);
            ldgA(s + 1, 1);
            cpaB(s + 1, pn); CP_COMMIT();
        }
        mmaKs(pm, 2);
        mmaKs(pm, 3);
        if (s1) stsA(pn, 1);
        CP_WAIT0();
        pm = pn;
    }

    // fused epilogue: + alpha, sigmoid, store
#pragma unroll
    for (int rt = 0; rt < 2; rt++) {
        const int r0 = rt0 + wr * 32 + rt * 16 + (l >> 2);
#pragma unroll
        for (int nt = 0; nt < 4; nt++) {
            const int u = wc * 32 + nt * 8 + (l & 3) * 2;
            const size_t idx0 = ((size_t)b * NM + r0) * Uq + u;
            const size_t idx8 = idx0 + 8 * Uq;
            float2 a0 = *(const float2*)&g_alpha[idx0];
            float2 a1 = *(const float2*)&g_alpha[idx8];
            float2 o0, o1;
            o0.x = 1.0f / (1.0f + __expf(-(acc[rt][nt][0] + a0.x)));
            o0.y = 1.0f / (1.0f + __expf(-(acc[rt][nt][1] + a0.y)));
            o1.x = 1.0f / (1.0f + __expf(-(acc[rt][nt][2] + a1.x)));
            o1.y = 1.0f / (1.0f + __expf(-(acc[rt][nt][3] + a1.y)));
            *(float2*)&out[idx0] = o0;
            *(float2*)&out[idx8] = o1;
        }
    }
}

// ---------------------------------------------------------------------------
extern "C" void kernel_launch(void* const* d_in, const int* in_sizes, int n_in,
                              void* d_out, int out_size) {
    const float* seq   = (const float*)d_in[0];   // (B,N,F)
    const float* graph = (const float*)d_in[1];   // (B,N,N,M)
    const float* e_w   = (const float*)d_in[2];   // (F,U)
    const float* v_w   = (const float*)d_in[3];   // (F,M,U)
    float* out = (float*)d_out;                   // (B,N,M,U)

    cudaFuncSetAttribute(precompute_mma_kernel,
                         cudaFuncAttributeMaxDynamicSharedMemorySize, SMEM_PRE);
    cudaFuncSetAttribute(multigraph_mma_kernel,
                         cudaFuncAttributeMaxDynamicSharedMemorySize, SMEM_MAIN);

    dim3 gridP(9, 32);
    precompute_mma_kernel<<<gridP, 256, SMEM_PRE>>>(seq, e_w, v_w);

    dim3 gridB(256, Bq);
    multigraph_mma_kernel<<<gridB, 128, SMEM_MAIN>>>(graph, out);
    (void)in_sizes; (void)n_in; (void)out_size;
}

// round 16
// speedup vs baseline: 1.5632x; 1.5632x over previous
#include <cuda_runtime.h>
#include <cuda_bf16.h>
#include <math.h>

#define Bq 2
#define Nq 2048
#define Fq 128
#define Mq 8
#define Uq 64
#define NM (Nq * Mq)            // 16384 rows of A'
#define OUTSZ (Bq * Nq * Mq * Uq)

#define JC 64                   // j per stage (main)
#define NSTAGE (Nq / JC)        // 32

// ---- main kernel smem: 2-buffer ring (R13 layout).
// A: j-major [64 j][128 rows bf16 = 256B, XOR-swizzled 16B chunks] hi+lo.
// B: [64 u][64 j bf16 = 128B data, stride 144] hi+lo (filled via cp.async).
#define SAJ 256
#define SBJ 144
#define AH_OFF 0
#define AL_OFF (AH_OFF + 64 * SAJ)      // 16384
#define BH_OFF (AL_OFF + 64 * SAJ)      // 32768
#define BL_OFF (BH_OFF + 64 * SBJ)      // 41984
#define BUF_SZ (BL_OFF + 64 * SBJ)      // 51200
#define SMEM_MAIN (2 * BUF_SZ)          // 102400

// ---- precompute-mma smem (unchanged)
#define SA2 272
#define P_AH 0
#define P_AL (P_AH + 128 * SA2)
#define P_WH (P_AL + 128 * SA2)
#define P_WL (P_WH + 64 * SA2)
#define SMEM_PRE (P_WL + 64 * SA2)      // 104448
#define CS 66
#define WS 69

// device scratch (allocation-free rule)
__device__ float g_alpha[OUTSZ];
__device__ unsigned short g_bTh[Bq * Uq * Nq];   // betaT hi bf16 [b][u][n]
__device__ unsigned short g_bTl[Bq * Uq * Nq];   // betaT lo bf16

__device__ __forceinline__ unsigned smem_u32(const void* p) {
    unsigned r;
    asm("{ .reg .u64 t; cvta.to.shared.u64 t, %1; cvt.u32.u64 %0, t; }"
        : "=r"(r) : "l"(p));
    return r;
}
__device__ __forceinline__ unsigned cvt_bf16x2(float lo_elem, float hi_elem) {
    unsigned r;   // low 16 bits <- lo_elem, high <- hi_elem
    asm("cvt.rn.bf16x2.f32 %0, %1, %2;" : "=r"(r) : "f"(hi_elem), "f"(lo_elem));
    return r;
}
__device__ __forceinline__ float bf_lo_f(unsigned h) { return __uint_as_float(h << 16); }
__device__ __forceinline__ float bf_hi_f(unsigned h) { return __uint_as_float(h & 0xffff0000u); }

#define LDSM4(r0, r1, r2, r3, addr) \
    asm volatile("ldmatrix.sync.aligned.m8n8.x4.shared.b16 {%0,%1,%2,%3}, [%4];" \
                 : "=r"(r0), "=r"(r1), "=r"(r2), "=r"(r3) : "r"(addr))

#define LDSM4T(r0, r1, r2, r3, addr) \
    asm volatile("ldmatrix.sync.aligned.m8n8.x4.trans.shared.b16 {%0,%1,%2,%3}, [%4];" \
                 : "=r"(r0), "=r"(r1), "=r"(r2), "=r"(r3) : "r"(addr))

#define CP_ASYNC16(dst, src) \
    asm volatile("cp.async.cg.shared.global [%0], [%1], 16;" :: "r"(dst), "l"(src))
#define CP_COMMIT() asm volatile("cp.async.commit_group;" ::: "memory")
#define CP_WAIT0()  asm volatile("cp.async.wait_group 0;" ::: "memory")

__device__ __forceinline__ void mma_bf16(float* c, const unsigned* a, const unsigned* b) {
    asm volatile(
        "mma.sync.aligned.m16n8k16.row.col.f32.bf16.bf16.f32 "
        "{%0,%1,%2,%3}, {%4,%5,%6,%7}, {%8,%9}, {%0,%1,%2,%3};"
        : "+f"(c[0]), "+f"(c[1]), "+f"(c[2]), "+f"(c[3])
        : "r"(a[0]), "r"(a[1]), "r"(a[2]), "r"(a[3]), "r"(b[0]), "r"(b[1]));
}

// ---------------------------------------------------------------------------
// Kernel P: beta|alpha = seq @ [e_w | v_w]  (UNCHANGED)
// ---------------------------------------------------------------------------
__global__ void __launch_bounds__(256, 2) precompute_mma_kernel(
        const float* __restrict__ seq,
        const float* __restrict__ e_w,
        const float* __restrict__ v_w) {
    extern __shared__ __align__(16) char ps[];
    const unsigned sb = smem_u32(ps);

    const int tid = threadIdx.x;
    const int l = tid & 31;
    const int w = tid >> 5;
    const int wr = w >> 1;
    const int wc = w & 1;

    const int bx = blockIdx.x;
    const int by = blockIdx.y;
    const int n0 = by * 128;

    {
        const float* wsrc;
        int wstride, c0;
        if (bx == 0) { wsrc = e_w; wstride = Uq;      c0 = 0; }
        else         { wsrc = v_w; wstride = Mq * Uq; c0 = (bx - 1) * 64; }
        float* wb = (float*)ps;
#pragma unroll
        for (int it = 0; it < 8; it++) {
            int v = tid + it * 256;
            int f = v >> 4, cq = (v & 15) * 4;
            float4 t = *(const float4*)&wsrc[f * wstride + c0 + cq];
            wb[f * WS + cq + 0] = t.x; wb[f * WS + cq + 1] = t.y;
            wb[f * WS + cq + 2] = t.z; wb[f * WS + cq + 3] = t.w;
        }
    }
    __syncthreads();

    {
        const float* wb = (const float*)ps;
        const int c = tid >> 2;
        const int fq8 = tid & 3;
#pragma unroll
        for (int it = 0; it < 4; it++) {
            int f0 = (fq8 + it * 4) * 8;
            unsigned h[4], lo[4];
#pragma unroll
            for (int k = 0; k < 4; k++) {
                float a0 = wb[(f0 + 2 * k) * WS + c];
                float a1 = wb[(f0 + 2 * k + 1) * WS + c];
                h[k] = cvt_bf16x2(a0, a1);
                float r0 = a0 - bf_lo_f(h[k]);
                float r1 = a1 - bf_hi_f(h[k]);
                lo[k] = cvt_bf16x2(r0, r1);
            }
            unsigned off = (unsigned)c * SA2 + f0 * 2;
            *(uint4*)(ps + P_WH + off) = make_uint4(h[0], h[1], h[2], h[3]);
            *(uint4*)(ps + P_WL + off) = make_uint4(lo[0], lo[1], lo[2], lo[3]);
        }
    }
    __syncthreads();

#pragma unroll
    for (int it = 0; it < 16; it++) {
        int v = tid + it * 256;
        int r = v >> 5, fq = v & 31;
        float4 t = *(const float4*)&seq[(size_t)(n0 + r) * Fq + fq * 4];
        unsigned h0 = cvt_bf16x2(t.x, t.y), h1 = cvt_bf16x2(t.z, t.w);
        unsigned l0 = cvt_bf16x2(t.x - bf_lo_f(h0), t.y - bf_hi_f(h0));
        unsigned l1 = cvt_bf16x2(t.z - bf_lo_f(h1), t.w - bf_hi_f(h1));
        unsigned off = (unsigned)r * SA2 + fq * 8;
        *(uint2*)(ps + P_AH + off) = make_uint2(h0, h1);
        *(uint2*)(ps + P_AL + off) = make_uint2(l0, l1);
    }
    __syncthreads();

    float acc[2][4][4];
#pragma unroll
    for (int rt = 0; rt < 2; rt++)
#pragma unroll
        for (int nt = 0; nt < 4; nt++)
#pragma unroll
            for (int k = 0; k < 4; k++) acc[rt][nt][k] = 0.f;

    const unsigned aRow = (unsigned)(wr * 32 + (l & 15)) * SA2 + ((l >> 4) * 16);
    const unsigned bRow = (unsigned)(wc * 32 + (l & 7) + ((l >> 4) & 1) * 8) * SA2
                        + (((l >> 3) & 1) * 16);

#pragma unroll
    for (int ks = 0; ks < 8; ks++) {
        unsigned ah[2][4], al[2][4], bh[8], bl[8];
#pragma unroll
        for (int rt = 0; rt < 2; rt++) {
            unsigned aoff = aRow + (unsigned)rt * 16 * SA2 + ks * 32;
            LDSM4(ah[rt][0], ah[rt][1], ah[rt][2], ah[rt][3], sb + P_AH + aoff);
            LDSM4(al[rt][0], al[rt][1], al[rt][2], al[rt][3], sb + P_AL + aoff);
        }
#pragma unroll
        for (int g = 0; g < 2; g++) {
            unsigned boff = bRow + (unsigned)g * 16 * SA2 + ks * 32;
            LDSM4(bh[g*4+0], bh[g*4+1], bh[g*4+2], bh[g*4+3], sb + P_WH + boff);
            LDSM4(bl[g*4+0], bl[g*4+1], bl[g*4+2], bl[g*4+3], sb + P_WL + boff);
        }
#pragma unroll
        for (int rt = 0; rt < 2; rt++)
#pragma unroll
            for (int nt = 0; nt < 4; nt++) {
                mma_bf16(acc[rt][nt], ah[rt], &bh[nt * 2]);
                mma_bf16(acc[rt][nt], al[rt], &bh[nt * 2]);
                mma_bf16(acc[rt][nt], ah[rt], &bl[nt * 2]);
            }
    }

    if (bx > 0) {
        const int c0 = (bx - 1) * 64;
#pragma unroll
        for (int rt = 0; rt < 2; rt++) {
            const int r0 = n0 + wr * 32 + rt * 16 + (l >> 2);
#pragma unroll
            for (int nt = 0; nt < 4; nt++) {
                const int cu = c0 + wc * 32 + nt * 8 + (l & 3) * 2;
                const size_t idx0 = (size_t)r0 * (Mq * Uq) + cu;
                const size_t idx8 = idx0 + 8 * (Mq * Uq);
                *(float2*)&g_alpha[idx0] = make_float2(acc[rt][nt][0], acc[rt][nt][1]);
                *(float2*)&g_alpha[idx8] = make_float2(acc[rt][nt][2], acc[rt][nt][3]);
            }
        }
    } else {
        __syncthreads();
        float* cs = (float*)ps;
#pragma unroll
        for (int rt = 0; rt < 2; rt++) {
            const int r0 = wr * 32 + rt * 16 + (l >> 2);
#pragma unroll
            for (int nt = 0; nt < 4; nt++) {
                const int u = wc * 32 + nt * 8 + (l & 3) * 2;
                *(float2*)&cs[r0 * CS + u] = make_float2(acc[rt][nt][0], acc[rt][nt][1]);
                *(float2*)&cs[(r0 + 8) * CS + u] = make_float2(acc[rt][nt][2], acc[rt][nt][3]);
            }
        }
        __syncthreads();
        const int b   = n0 >> 11;
        const int nin = n0 & 2047;
        const int u  = tid >> 2;
        const int nq = tid & 3;
#pragma unroll
        for (int it = 0; it < 8; it++) {
            int n = nq * 4 + it * 16;
            float v0 = cs[(n + 0) * CS + u], v1 = cs[(n + 1) * CS + u];
            float v2 = cs[(n + 2) * CS + u], v3 = cs[(n + 3) * CS + u];
            unsigned h01 = cvt_bf16x2(v0, v1), h23 = cvt_bf16x2(v2, v3);
            unsigned l01 = cvt_bf16x2(v0 - bf_lo_f(h01), v1 - bf_hi_f(h01));
            unsigned l23 = cvt_bf16x2(v2 - bf_lo_f(h23), v3 - bf_hi_f(h23));
            size_t idx = (size_t)(b * Uq + u) * Nq + nin + n;
            *(uint2*)&g_bTh[idx] = make_uint2(h01, h23);
            *(uint2*)&g_bTl[idx] = make_uint2(l01, l23);
        }
    }
}

// ---------------------------------------------------------------------------
// Kernel B (main): exact R13 structure (JC=64, 2-buffer ring, 256 thr, 2/SM).
// ONLY change: mmaKs interleaves LDSM groups with HMMA bursts so LDSM latency
// hides under tensor work instead of stacking at the k-step head.
// ---------------------------------------------------------------------------
__global__ void __launch_bounds__(256, 2) multigraph_mma_kernel(
        const float* __restrict__ graph,
        float* __restrict__ out) {
    extern __shared__ __align__(16) char smem[];
    const unsigned sb = smem_u32(smem);

    const int tid = threadIdx.x;
    const int l = tid & 31;
    const int w = tid >> 5;
    const int wr = w >> 1;                   // 0..3 (32 rows)
    const int wc = w & 1;                    // 0..1 (32 u)

    const int rt0 = blockIdx.x * 128;        // global A' row base
    const int b   = blockIdx.y;
    const int i0  = rt0 >> 3;

    // A staging: lane pair covers (jp, mq); thread covers 8 il in 2 halves
    const int mq  = tid & 1;
    const int jp  = (tid >> 1) & 63;         // 0..63
    const int ilg = tid >> 7;                // 0..1
    const int jp15 = jp & 15;
    // B cp.async mapping
    const int bu0 = tid >> 3;                // 0..31
    const int bjq = tid & 7;

    float acc[2][4][4];
#pragma unroll
    for (int rt = 0; rt < 2; rt++)
#pragma unroll
        for (int nt = 0; nt < 4; nt++)
#pragma unroll
            for (int k = 0; k < 4; k++) acc[rt][nt][k] = 0.f;

    // ldmatrix lane constants
    const int jl15 = (l & 7) + ((l >> 4) & 1) * 8;   // j within 16-group
    const int cpart = (l >> 3) & 1;                   // 8-row subgroup
    const unsigned bRow = (unsigned)(wc * 32 + (l & 7) + ((l >> 4) & 1) * 8) * SBJ
                        + (unsigned)(cpart * 16);

    const size_t gbase = ((size_t)b * Nq + i0) * Nq * Mq;
    const size_t bTb = (size_t)b * Uq * Nq;

    float4 av[4];

    auto ldgA = [&](int s, int h) {
        const int j0 = s * JC;
#pragma unroll
        for (int c = 0; c < 4; c++) {
            int il = (h * 4 + c) * 2 + ilg;
            av[c] = *(const float4*)(graph + gbase
                        + ((size_t)il * Nq + j0 + jp) * Mq + mq * 4);
        }
    };
    auto stsA = [&](int p, int h) {
        char* buf = smem + p * BUF_SZ;
#pragma unroll
        for (int c = 0; c < 4; c++) {
            int il = (h * 4 + c) * 2 + ilg;      // chunk index 0..15
            const float* v = (const float*)&av[c];
            unsigned h0 = cvt_bf16x2(v[0], v[1]);
            unsigned h1 = cvt_bf16x2(v[2], v[3]);
            unsigned l0 = cvt_bf16x2(v[0] - bf_lo_f(h0), v[1] - bf_hi_f(h0));
            unsigned l1 = cvt_bf16x2(v[2] - bf_lo_f(h1), v[3] - bf_hi_f(h1));
            unsigned off = (unsigned)jp * SAJ + (unsigned)((il ^ jp15) << 4)
                         + (unsigned)(mq * 8);
            *(uint2*)(buf + AH_OFF + off) = make_uint2(h0, h1);
            *(uint2*)(buf + AL_OFF + off) = make_uint2(l0, l1);
        }
    };
    auto cpaB = [&](int s, int p) {
        const int j0 = s * JC;
        const unsigned dbase = sb + (unsigned)p * BUF_SZ;
#pragma unroll
        for (int it = 0; it < 2; it++) {
            int u = bu0 + it * 32;
            size_t src = bTb + (size_t)u * Nq + j0 + bjq * 8;
            unsigned doff = (unsigned)u * SBJ + bjq * 16;
            CP_ASYNC16(dbase + BH_OFF + doff, (const char*)&g_bTh[src]);
            CP_ASYNC16(dbase + BL_OFF + doff, (const char*)&g_bTl[src]);
        }
    };
    auto mmaKs = [&](int p, int ks) {
        const unsigned base = sb + (unsigned)p * BUF_SZ;
        const int jrow = jl15 + ks * 16;
        unsigned ah[2][4], al[2][4], bh[8], bl[8];
        // group 1: A rt0 + B g0
        {
            int chunk = wr * 4 + 0 * 2 + cpart;
            unsigned aoff = (unsigned)jrow * SAJ + (unsigned)((chunk ^ jl15) << 4);
            LDSM4T(ah[0][0], ah[0][1], ah[0][2], ah[0][3], base + AH_OFF + aoff);
            LDSM4T(al[0][0], al[0][1], al[0][2], al[0][3], base + AL_OFF + aoff);
            unsigned boff = bRow + ks * 32;
            LDSM4(bh[0], bh[1], bh[2], bh[3], base + BH_OFF + boff);
            LDSM4(bl[0], bl[1], bl[2], bl[3], base + BL_OFF + boff);
        }
        // HMMA burst 1: rt0 x nt0,nt1 (hides group-2 LDSM below)
#pragma unroll
        for (int nt = 0; nt < 2; nt++) {
            mma_bf16(acc[0][nt], ah[0], &bh[nt * 2]);
            mma_bf16(acc[0][nt], al[0], &bh[nt * 2]);
            mma_bf16(acc[0][nt], ah[0], &bl[nt * 2]);
        }
        // group 2: A rt1 + B g1
        {
            int chunk = wr * 4 + 1 * 2 + cpart;
            unsigned aoff = (unsigned)jrow * SAJ + (unsigned)((chunk ^ jl15) << 4);
            LDSM4T(ah[1][0], ah[1][1], ah[1][2], ah[1][3], base + AH_OFF + aoff);
            LDSM4T(al[1][0], al[1][1], al[1][2], al[1][3], base + AL_OFF + aoff);
            unsigned boff = bRow + 16 * SBJ + ks * 32;
            LDSM4(bh[4], bh[5], bh[6], bh[7], base + BH_OFF + boff);
            LDSM4(bl[4], bl[5], bl[6], bl[7], base + BL_OFF + boff);
        }
        // HMMA burst 2: rt1 x nt0,nt1
#pragma unroll
        for (int nt = 0; nt < 2; nt++) {
            mma_bf16(acc[1][nt], ah[1], &bh[nt * 2]);
            mma_bf16(acc[1][nt], al[1], &bh[nt * 2]);
            mma_bf16(acc[1][nt], ah[1], &bl[nt * 2]);
        }
        // HMMA burst 3: rt0,rt1 x nt2,nt3
#pragma unroll
        for (int rt = 0; rt < 2; rt++)
#pragma unroll
            for (int nt = 2; nt < 4; nt++) {
                mma_bf16(acc[rt][nt], ah[rt], &bh[nt * 2]);
                mma_bf16(acc[rt][nt], al[rt], &bh[nt * 2]);
                mma_bf16(acc[rt][nt], ah[rt], &bl[nt * 2]);
            }
    };

    // prologue: stage 0 fully staged into buffer 0
    ldgA(0, 0); stsA(0, 0);
    ldgA(0, 1); stsA(0, 1);
    cpaB(0, 0); CP_COMMIT();
    CP_WAIT0();

    int pm = 0;
#pragma unroll 1
    for (int s = 0; s < NSTAGE; s++) {
        __syncthreads();                     // buf pm ready; buf pn free
        const int pn = pm ^ 1;
        const bool s1 = (s + 1 < NSTAGE);
        if (s1) ldgA(s + 1, 0);
        mmaKs(pm, 0);
        mmaKs(pm, 1);
        if (s1) {
            stsA(pn, 0);
            ldgA(s + 1, 1);
            cpaB(s + 1, pn); CP_COMMIT();
        }
        mmaKs(pm, 2);
        mmaKs(pm, 3);
        if (s1) stsA(pn, 1);
        CP_WAIT0();
        pm = pn;
    }

    // fused epilogue: + alpha, sigmoid, store
#pragma unroll
    for (int rt = 0; rt < 2; rt++) {
        const int r0 = rt0 + wr * 32 + rt * 16 + (l >> 2);
#pragma unroll
        for (int nt = 0; nt < 4; nt++) {
            const int u = wc * 32 + nt * 8 + (l & 3) * 2;
            const size_t idx0 = ((size_t)b * NM + r0) * Uq + u;
            const size_t idx8 = idx0 + 8 * Uq;
            float2 a0 = *(const float2*)&g_alpha[idx0];
            float2 a1 = *(const float2*)&g_alpha[idx8];
            float2 o0, o1;
            o0.x = 1.0f / (1.0f + __expf(-(acc[rt][nt][0] + a0.x)));
            o0.y = 1.0f / (1.0f + __expf(-(acc[rt][nt][1] + a0.y)));
            o1.x = 1.0f / (1.0f + __expf(-(acc[rt][nt][2] + a1.x)));
            o1.y = 1.0f / (1.0f + __expf(-(acc[rt][nt][3] + a1.y)));
            *(float2*)&out[idx0] = o0;
            *(float2*)&out[idx8] = o1;
        }
    }
}

// ---------------------------------------------------------------------------
extern "C" void kernel_launch(void* const* d_in, const int* in_sizes, int n_in,
                              void* d_out, int out_size) {
    const float* seq   = (const float*)d_in[0];   // (B,N,F)
    const float* graph = (const float*)d_in[1];   // (B,N,N,M)
    const float* e_w   = (const float*)d_in[2];   // (F,U)
    const float* v_w   = (const float*)d_in[3];   // (F,M,U)
    float* out = (float*)d_out;                   // (B,N,M,U)

    cudaFuncSetAttribute(precompute_mma_kernel,
                         cudaFuncAttributeMaxDynamicSharedMemorySize, SMEM_PRE);
    cudaFuncSetAttribute(multigraph_mma_kernel,
                         cudaFuncAttributeMaxDynamicSharedMemorySize, SMEM_MAIN);

    dim3 gridP(9, 32);
    precompute_mma_kernel<<<gridP, 256, SMEM_PRE>>>(seq, e_w, v_w);

    dim3 gridB(128, Bq);
    multigraph_mma_kernel<<<gridB, 256, SMEM_MAIN>>>(graph, out);
    (void)in_sizes; (void)n_in; (void)out_size;
}